// round 8
// baseline (speedup 1.0000x reference)
#include <cuda_runtime.h>
#include <cuda_fp16.h>
#include <cstdint>
#include <math.h>

#define BATCH 512
#define NSEQ  128
#define DDIM  128
#define BIGF 1e30f

#define NCTA  148
#define NDIAG 255           // 2*NSEQ-1
#define P2    68            // staging pitch (floats); 68 mod 32 = 4 -> conflict-free frags
#define DP_H  132           // diag pitch in halves (264 B: 8B-aligned uint2)
#define BUF_WORDS (2 * NSEQ * P2)              // 17408 floats = 69632 B per buffer
#define SM_DYN_BYTES (3 * BUF_WORDS * 4)       // 208896 B

// Named barriers: full[ib] = 1+ib (ib=0..3, count 288), empty(buf0 reuse) = 5
// (count 288), MMA-internal = 7 (count 256).

__device__ float g_dtw[BATCH];
__device__ int   g_ctr = 0;

__device__ __forceinline__ void barsync(int id, int cnt) {
    asm volatile("bar.sync %0, %1;" :: "r"(id), "r"(cnt) : "memory");
}
__device__ __forceinline__ void bararrive(int id, int cnt) {
    asm volatile("bar.arrive %0, %1;" :: "r"(id), "r"(cnt) : "memory");
}
__device__ __forceinline__ float f2tf32f(float v) {
    uint32_t r;
    asm("cvt.rna.tf32.f32 %0, %1;" : "=r"(r) : "f"(v));
    return __uint_as_float(r);
}
__device__ __forceinline__ void mma_tf32(float c[4], const uint32_t a[4],
                                         const uint32_t b[2]) {
    asm volatile(
        "mma.sync.aligned.m16n8k8.row.col.f32.tf32.tf32.f32 "
        "{%0,%1,%2,%3}, {%4,%5,%6,%7}, {%8,%9}, {%0,%1,%2,%3};\n"
        : "+f"(c[0]), "+f"(c[1]), "+f"(c[2]), "+f"(c[3])
        : "r"(a[0]), "r"(a[1]), "r"(a[2]), "r"(a[3]), "r"(b[0]), "r"(b[1]));
}

__global__ __launch_bounds__(384, 1) void fused_kernel(const float* __restrict__ X,
                                                       const float* __restrict__ Y,
                                                       float* __restrict__ out) {
    extern __shared__ float sm[];
    __shared__ float xxs[NSEQ], yys[NSEQ];

    const int tid = threadIdx.x, w = tid >> 5, lane = tid & 31;
    const int c = blockIdx.x;
    const int nb = (c < BATCH - 3 * NCTA) ? 4 : 3;   // 4 for c<68, else 3

    if (w < 8) {
        // ================= MMA role: threads 0..255 =================
        const int qr = lane >> 2, qc = lane & 3;
        const int m0 = (w & 1) * 64, n0 = (w >> 1) * 32;

        for (int ib = 0; ib < nb; ib++) {
            const int b = c + ib * NCTA;
            const int p = ib % 3;
            float* buf = sm + p * BUF_WORDS;
            float* Xs = buf;
            float* Ys = buf + NSEQ * P2;

            if (ib == 3) barsync(5, 288);          // wait DP warp 0 to free buf 0

            float acc[4][4][4];
            #pragma unroll
            for (int mt = 0; mt < 4; mt++)
                #pragma unroll
                for (int nt = 0; nt < 4; nt++)
                    #pragma unroll
                    for (int r = 0; r < 4; r++) acc[mt][nt][r] = 0.f;

            float nrm = 0.f;

            #pragma unroll
            for (int ph = 0; ph < 2; ph++) {
                if (ph) barsync(7, 256);
                #pragma unroll
                for (int s = 0; s < 8; s++) {
                    int idx = s * 256 + tid;       // 0..2047
                    int r = idx >> 4, c4 = (idx & 15) << 2;
                    float4 xv = *(const float4*)(X + (size_t)b * NSEQ * DDIM + r * DDIM + ph * 64 + c4);
                    float4 yv = *(const float4*)(Y + (size_t)b * NSEQ * DDIM + r * DDIM + ph * 64 + c4);
                    xv.x = f2tf32f(xv.x); xv.y = f2tf32f(xv.y);
                    xv.z = f2tf32f(xv.z); xv.w = f2tf32f(xv.w);
                    yv.x = f2tf32f(yv.x); yv.y = f2tf32f(yv.y);
                    yv.z = f2tf32f(yv.z); yv.w = f2tf32f(yv.w);
                    *(float4*)&Xs[r * P2 + c4] = xv;
                    *(float4*)&Ys[r * P2 + c4] = yv;
                }
                barsync(7, 256);

                {   // norm partials (tf32-rounded inputs)
                    int r = tid & 127;
                    const float* src = (tid < NSEQ) ? Xs : Ys;
                    float s = 0.f;
                    #pragma unroll
                    for (int cc = 0; cc < 64; cc += 4) {
                        float4 v = *(const float4*)&src[r * P2 + cc];
                        s = fmaf(v.x, v.x, fmaf(v.y, v.y, fmaf(v.z, v.z, fmaf(v.w, v.w, s))));
                    }
                    nrm += s;
                }

                #pragma unroll 1
                for (int k0 = 0; k0 < 64; k0 += 8) {
                    uint32_t aF[4][4], bF[4][2];
                    #pragma unroll
                    for (int mt = 0; mt < 4; mt++) {
                        const float* ab = &Xs[(m0 + mt * 16 + qr) * P2 + k0 + qc];
                        aF[mt][0] = __float_as_uint(ab[0]);
                        aF[mt][1] = __float_as_uint(ab[8 * P2]);
                        aF[mt][2] = __float_as_uint(ab[4]);
                        aF[mt][3] = __float_as_uint(ab[8 * P2 + 4]);
                    }
                    #pragma unroll
                    for (int nt = 0; nt < 4; nt++) {
                        const float* bb = &Ys[(n0 + nt * 8 + qr) * P2 + k0 + qc];
                        bF[nt][0] = __float_as_uint(bb[0]);
                        bF[nt][1] = __float_as_uint(bb[4]);
                    }
                    #pragma unroll
                    for (int mt = 0; mt < 4; mt++)
                        #pragma unroll
                        for (int nt = 0; nt < 4; nt++)
                            mma_tf32(acc[mt][nt], aF[mt], bF[nt]);
                }
            }

            if (tid < NSEQ) xxs[tid] = nrm; else yys[tid - NSEQ] = nrm;
            barsync(7, 256);   // staging reads done; buf reusable; norms visible

            // fill diag area with fp16 +inf (invalid cells self-mask in the DP)
            {
                uint4 inf4 = make_uint4(0x7C007C00u, 0x7C007C00u, 0x7C007C00u, 0x7C007C00u);
                uint4* bv = (uint4*)buf;
                #pragma unroll
                for (int i = tid; i < (NDIAG * DP_H * 2 + 15) / 16; i += 256) bv[i] = inf4;
            }
            barsync(7, 256);

            // epilogue: D = xx + yy - 2*xy -> fp16, diag-major (indexed by column j)
            __half* Dd = (__half*)buf;   // [255][132] halves
            #pragma unroll
            for (int mt = 0; mt < 4; mt++) {
                int i0 = m0 + mt * 16 + qr;
                float xv0 = xxs[i0], xv1 = xxs[i0 + 8];
                #pragma unroll
                for (int nt = 0; nt < 4; nt++) {
                    int j0 = n0 + nt * 8 + 2 * qc;
                    float yv0 = yys[j0], yv1 = yys[j0 + 1];
                    const float* cA = acc[mt][nt];
                    Dd[(i0 + j0)         * DP_H + j0]     = __float2half(xv0 + yv0 - 2.f * cA[0]);
                    Dd[(i0 + j0 + 1)     * DP_H + j0 + 1] = __float2half(xv0 + yv1 - 2.f * cA[1]);
                    Dd[(i0 + 8 + j0)     * DP_H + j0]     = __float2half(xv1 + yv0 - 2.f * cA[2]);
                    Dd[(i0 + 8 + j0 + 1) * DP_H + j0 + 1] = __float2half(xv1 + yv1 - 2.f * cA[3]);
                }
            }
            barsync(7, 256);               // epilogue complete
            bararrive(1 + ib, 288);        // signal full[ib]
        }
    } else {
        // ========== DP role: warps 8..11, one batch each, skewed wavefront ==========
        const int d = w - 8, l = lane;
        if (d < nb) {
            const int b = c + d * NCTA;
            const __half* Dd = (const __half*)(sm + (d % 3) * BUF_WORDS);

            barsync(1 + d, 288);           // wait full[d]

            // Skew: lane l processes diagonal k = s - l at step s (transposed DP;
            // DTW(D^T) == DTW(D)). Lane owns columns j = 4l..4l+3. Invalid cells
            // are +inf from the buffer fill; boundary shfl has 2 steps of slack.
            float A0 = BIGF, A1 = BIGF, A2 = BIGF, A3 = BIGF;
            float B0 = BIGF, B1 = BIGF, B2 = BIGF, B3 = BIGF;
            float uE = BIGF, uO = BIGF;    // boundary delay line (even/odd slots)
            const int zstep = (l == 0) ? 0 : -1;

            const __half* base = Dd + 4 * l;
            auto ldD = [&](int s_) -> uint2 {
                int k = s_ - l;
                k = k < 0 ? 0 : (k > NDIAG - 1 ? NDIAG - 1 : k);
                return *(const uint2*)(base + k * DP_H);
            };
            uint2 q0 = ldD(0), q1 = ldD(1);

            #pragma unroll 1
            for (int s = 0; s < 286; s += 2) {
                // even step: km1 = A, km2 = B -> write B
                float recv = __shfl_up_sync(0xffffffffu, A3, 1);
                recv = (l == 0) ? BIGF : recv;
                uint2 dq = q0; q0 = ldD(s + 2);
                float2 f01 = __half22float2(*(__half2*)&dq.x);
                float2 f23 = __half22float2(*(__half2*)&dq.y);
                {
                    float dg0 = (s == zstep) ? 0.f : uE;
                    float t0 = f01.x + fminf(fminf(dg0, uO), A0);
                    float t1 = f01.y + fminf(fminf(B0, A0), A1);
                    float t2 = f23.x + fminf(fminf(B1, A1), A2);
                    float t3 = f23.y + fminf(fminf(B2, A2), A3);
                    B0 = t0; B1 = t1; B2 = t2; B3 = t3;
                }
                uE = recv;

                // odd step: km1 = B, km2 = A -> write A   (zero-case impossible)
                recv = __shfl_up_sync(0xffffffffu, B3, 1);
                recv = (l == 0) ? BIGF : recv;
                dq = q1; q1 = ldD(s + 3);
                f01 = __half22float2(*(__half2*)&dq.x);
                f23 = __half22float2(*(__half2*)&dq.y);
                {
                    float t0 = f01.x + fminf(fminf(uO, uE), B0);
                    float t1 = f01.y + fminf(fminf(A0, B0), B1);
                    float t2 = f23.x + fminf(fminf(A1, B1), B2);
                    float t3 = f23.y + fminf(fminf(A2, B2), B3);
                    A0 = t0; A1 = t1; A2 = t2; A3 = t3;
                }
                uO = recv;
            }
            // lane 31's last write: step 285 (odd) -> A3 = R[127][127] (k = 254)
            if (l == 31) {
                g_dtw[b] = A3;
                __threadfence();
            }
            if (d == 0) bararrive(5, 288);     // free buf 0 for batch 3
        }
    }

    __syncthreads();

    if (tid == 0) {
        if (atomicAdd(&g_ctr, 1) == NCTA - 1) {
            __threadfence();
            // deterministic fixed-order reduction of g_dtw[0..511]
            float a0 = 0.f, a1 = 0.f, a2 = 0.f, a3 = 0.f;
            float a4 = 0.f, a5 = 0.f, a6 = 0.f, a7 = 0.f;
            for (int i = 0; i < BATCH; i += 32) {
                float4 v0 = *(const float4*)&g_dtw[i];
                float4 v1 = *(const float4*)&g_dtw[i + 4];
                float4 v2 = *(const float4*)&g_dtw[i + 8];
                float4 v3 = *(const float4*)&g_dtw[i + 12];
                float4 v4 = *(const float4*)&g_dtw[i + 16];
                float4 v5 = *(const float4*)&g_dtw[i + 20];
                float4 v6 = *(const float4*)&g_dtw[i + 24];
                float4 v7 = *(const float4*)&g_dtw[i + 28];
                a0 += (v0.x + v0.y) + (v0.z + v0.w);
                a1 += (v1.x + v1.y) + (v1.z + v1.w);
                a2 += (v2.x + v2.y) + (v2.z + v2.w);
                a3 += (v3.x + v3.y) + (v3.z + v3.w);
                a4 += (v4.x + v4.y) + (v4.z + v4.w);
                a5 += (v5.x + v5.y) + (v5.z + v5.w);
                a6 += (v6.x + v6.y) + (v6.z + v6.w);
                a7 += (v7.x + v7.y) + (v7.z + v7.w);
            }
            float s = ((a0 + a1) + (a2 + a3)) + ((a4 + a5) + (a6 + a7));
            float E = s * (1.0f / (float)BATCH);
            out[0] = E;
            out[1] = 10.0f * sqrtf(E + 1e-10f);
            g_ctr = 0;   // reset for graph replay
        }
    }
}

extern "C" void kernel_launch(void* const* d_in, const int* in_sizes, int n_in,
                              void* d_out, int out_size) {
    const float* X = (const float*)d_in[0];   // outputs
    const float* Y = (const float*)d_in[1];   // targets
    float* out = (float*)d_out;

    cudaFuncSetAttribute(fused_kernel, cudaFuncAttributeMaxDynamicSharedMemorySize,
                         SM_DYN_BYTES);

    fused_kernel<<<NCTA, 384, SM_DYN_BYTES>>>(X, Y, out);
}

// round 9
// speedup vs baseline: 1.3050x; 1.3050x over previous
#include <cuda_runtime.h>
#include <cuda_fp16.h>
#include <cstdint>
#include <math.h>

#define BATCH 512
#define NSEQ  128
#define DDIM  128
#define BIGF 1e30f

#define NCTA  148
#define NDIAG 255           // 2*NSEQ-1
#define P2    68            // staging pitch (floats); 68 mod 32 = 4 -> conflict-free frags
#define DP_H  136           // diag pitch in halves (272 B). Skewed DP load: bank mult
                            // 2-68 = -66 = 30 mod 32 -> optimal 2-way. Epilogue store:
                            // bank = 4qr+9qc+c -> all 32 lanes distinct (conflict-free).
#define BUF_WORDS (2 * NSEQ * P2)              // 17408 floats = 69632 B per buffer
#define SM_DYN_BYTES (3 * BUF_WORDS * 4)       // 208896 B  (diag use: 69360 B <= buf)

// Named barriers: full[ib] = 1+ib (ib=0..3, count 288), empty(buf0 reuse) = 5
// (count 288), MMA-internal = 7 (count 256).

__device__ float g_dtw[BATCH];
__device__ int   g_ctr = 0;

__device__ __forceinline__ void barsync(int id, int cnt) {
    asm volatile("bar.sync %0, %1;" :: "r"(id), "r"(cnt) : "memory");
}
__device__ __forceinline__ void bararrive(int id, int cnt) {
    asm volatile("bar.arrive %0, %1;" :: "r"(id), "r"(cnt) : "memory");
}
__device__ __forceinline__ float f2tf32f(float v) {
    uint32_t r;
    asm("cvt.rna.tf32.f32 %0, %1;" : "=r"(r) : "f"(v));
    return __uint_as_float(r);
}
__device__ __forceinline__ void mma_tf32(float c[4], const uint32_t a[4],
                                         const uint32_t b[2]) {
    asm volatile(
        "mma.sync.aligned.m16n8k8.row.col.f32.tf32.tf32.f32 "
        "{%0,%1,%2,%3}, {%4,%5,%6,%7}, {%8,%9}, {%0,%1,%2,%3};\n"
        : "+f"(c[0]), "+f"(c[1]), "+f"(c[2]), "+f"(c[3])
        : "r"(a[0]), "r"(a[1]), "r"(a[2]), "r"(a[3]), "r"(b[0]), "r"(b[1]));
}

__global__ __launch_bounds__(384, 1) void fused_kernel(const float* __restrict__ X,
                                                       const float* __restrict__ Y,
                                                       float* __restrict__ out) {
    extern __shared__ float sm[];
    __shared__ float xxs[NSEQ], yys[NSEQ];

    const int tid = threadIdx.x, w = tid >> 5, lane = tid & 31;
    const int c = blockIdx.x;
    const int nb = (c < BATCH - 3 * NCTA) ? 4 : 3;   // 4 for c<68, else 3

    if (w < 8) {
        // ================= MMA role: threads 0..255 =================
        const int qr = lane >> 2, qc = lane & 3;
        const int m0 = (w & 1) * 64, n0 = (w >> 1) * 32;

        for (int ib = 0; ib < nb; ib++) {
            const int b = c + ib * NCTA;
            const int p = ib % 3;
            float* buf = sm + p * BUF_WORDS;
            float* Xs = buf;
            float* Ys = buf + NSEQ * P2;

            if (ib == 3) barsync(5, 288);          // wait DP warp 0 to free buf 0

            float acc[4][4][4];
            #pragma unroll
            for (int mt = 0; mt < 4; mt++)
                #pragma unroll
                for (int nt = 0; nt < 4; nt++)
                    #pragma unroll
                    for (int r = 0; r < 4; r++) acc[mt][nt][r] = 0.f;

            float nrm = 0.f;

            #pragma unroll
            for (int ph = 0; ph < 2; ph++) {
                if (ph) barsync(7, 256);
                #pragma unroll
                for (int s = 0; s < 8; s++) {
                    int idx = s * 256 + tid;       // 0..2047
                    int r = idx >> 4, c4 = (idx & 15) << 2;
                    float4 xv = *(const float4*)(X + (size_t)b * NSEQ * DDIM + r * DDIM + ph * 64 + c4);
                    float4 yv = *(const float4*)(Y + (size_t)b * NSEQ * DDIM + r * DDIM + ph * 64 + c4);
                    xv.x = f2tf32f(xv.x); xv.y = f2tf32f(xv.y);
                    xv.z = f2tf32f(xv.z); xv.w = f2tf32f(xv.w);
                    yv.x = f2tf32f(yv.x); yv.y = f2tf32f(yv.y);
                    yv.z = f2tf32f(yv.z); yv.w = f2tf32f(yv.w);
                    *(float4*)&Xs[r * P2 + c4] = xv;
                    *(float4*)&Ys[r * P2 + c4] = yv;
                }
                barsync(7, 256);

                {   // norm partials (tf32-rounded inputs)
                    int r = tid & 127;
                    const float* src = (tid < NSEQ) ? Xs : Ys;
                    float s = 0.f;
                    #pragma unroll
                    for (int cc = 0; cc < 64; cc += 4) {
                        float4 v = *(const float4*)&src[r * P2 + cc];
                        s = fmaf(v.x, v.x, fmaf(v.y, v.y, fmaf(v.z, v.z, fmaf(v.w, v.w, s))));
                    }
                    nrm += s;
                }

                #pragma unroll 1
                for (int k0 = 0; k0 < 64; k0 += 8) {
                    uint32_t aF[4][4], bF[4][2];
                    #pragma unroll
                    for (int mt = 0; mt < 4; mt++) {
                        const float* ab = &Xs[(m0 + mt * 16 + qr) * P2 + k0 + qc];
                        aF[mt][0] = __float_as_uint(ab[0]);
                        aF[mt][1] = __float_as_uint(ab[8 * P2]);
                        aF[mt][2] = __float_as_uint(ab[4]);
                        aF[mt][3] = __float_as_uint(ab[8 * P2 + 4]);
                    }
                    #pragma unroll
                    for (int nt = 0; nt < 4; nt++) {
                        const float* bb = &Ys[(n0 + nt * 8 + qr) * P2 + k0 + qc];
                        bF[nt][0] = __float_as_uint(bb[0]);
                        bF[nt][1] = __float_as_uint(bb[4]);
                    }
                    #pragma unroll
                    for (int mt = 0; mt < 4; mt++)
                        #pragma unroll
                        for (int nt = 0; nt < 4; nt++)
                            mma_tf32(acc[mt][nt], aF[mt], bF[nt]);
                }
            }

            if (tid < NSEQ) xxs[tid] = nrm; else yys[tid - NSEQ] = nrm;
            barsync(7, 256);   // staging reads done; buf reusable; norms visible

            // fill diag area with fp16 +inf (invalid cells self-mask in the DP)
            {
                uint4 inf4 = make_uint4(0x7C007C00u, 0x7C007C00u, 0x7C007C00u, 0x7C007C00u);
                uint4* bv = (uint4*)buf;
                #pragma unroll
                for (int i = tid; i < NDIAG * DP_H * 2 / 16; i += 256) bv[i] = inf4;
            }
            barsync(7, 256);

            // epilogue: D = xx + yy - 2*xy -> fp16, diag-major (indexed by column j)
            __half* Dd = (__half*)buf;   // [255][136] halves = 69360 B
            #pragma unroll
            for (int mt = 0; mt < 4; mt++) {
                int i0 = m0 + mt * 16 + qr;
                float xv0 = xxs[i0], xv1 = xxs[i0 + 8];
                #pragma unroll
                for (int nt = 0; nt < 4; nt++) {
                    int j0 = n0 + nt * 8 + 2 * qc;
                    float yv0 = yys[j0], yv1 = yys[j0 + 1];
                    const float* cA = acc[mt][nt];
                    Dd[(i0 + j0)         * DP_H + j0]     = __float2half(xv0 + yv0 - 2.f * cA[0]);
                    Dd[(i0 + j0 + 1)     * DP_H + j0 + 1] = __float2half(xv0 + yv1 - 2.f * cA[1]);
                    Dd[(i0 + 8 + j0)     * DP_H + j0]     = __float2half(xv1 + yv0 - 2.f * cA[2]);
                    Dd[(i0 + 8 + j0 + 1) * DP_H + j0 + 1] = __float2half(xv1 + yv1 - 2.f * cA[3]);
                }
            }
            barsync(7, 256);               // epilogue complete
            bararrive(1 + ib, 288);        // signal full[ib]
        }
    } else {
        // ========== DP role: warps 8..11, one batch each, skewed wavefront ==========
        const int d = w - 8, l = lane;
        if (d < nb) {
            const int b = c + d * NCTA;
            const __half* Dd = (const __half*)(sm + (d % 3) * BUF_WORDS);

            barsync(1 + d, 288);           // wait full[d]

            // Skew: lane l processes diagonal k = s - l at step s (transposed DP;
            // DTW(D^T) == DTW(D)). Lane owns columns j = 4l..4l+3. Invalid cells
            // are +inf from the buffer fill; boundary shfl has 2 steps of slack.
            float A0 = BIGF, A1 = BIGF, A2 = BIGF, A3 = BIGF;
            float B0 = BIGF, B1 = BIGF, B2 = BIGF, B3 = BIGF;
            float uE = BIGF, uO = BIGF;    // boundary delay line (even/odd slots)
            const int zstep = (l == 0) ? 0 : -1;

            const __half* base = Dd + 4 * l;
            auto ldD = [&](int s_) -> uint2 {
                int k = s_ - l;
                k = k < 0 ? 0 : (k > NDIAG - 1 ? NDIAG - 1 : k);
                return *(const uint2*)(base + k * DP_H);
            };
            uint2 q0 = ldD(0), q1 = ldD(1);

            #pragma unroll 1
            for (int s = 0; s < 286; s += 2) {
                // even step: km1 = A, km2 = B -> write B
                float recv = __shfl_up_sync(0xffffffffu, A3, 1);
                recv = (l == 0) ? BIGF : recv;
                uint2 dq = q0; q0 = ldD(s + 2);
                float2 f01 = __half22float2(*(__half2*)&dq.x);
                float2 f23 = __half22float2(*(__half2*)&dq.y);
                {
                    float dg0 = (s == zstep) ? 0.f : uE;
                    float t0 = f01.x + fminf(fminf(dg0, uO), A0);
                    float t1 = f01.y + fminf(fminf(B0, A0), A1);
                    float t2 = f23.x + fminf(fminf(B1, A1), A2);
                    float t3 = f23.y + fminf(fminf(B2, A2), A3);
                    B0 = t0; B1 = t1; B2 = t2; B3 = t3;
                }
                uE = recv;

                // odd step: km1 = B, km2 = A -> write A   (zero-case impossible)
                recv = __shfl_up_sync(0xffffffffu, B3, 1);
                recv = (l == 0) ? BIGF : recv;
                dq = q1; q1 = ldD(s + 3);
                f01 = __half22float2(*(__half2*)&dq.x);
                f23 = __half22float2(*(__half2*)&dq.y);
                {
                    float t0 = f01.x + fminf(fminf(uO, uE), B0);
                    float t1 = f01.y + fminf(fminf(A0, B0), B1);
                    float t2 = f23.x + fminf(fminf(A1, B1), B2);
                    float t3 = f23.y + fminf(fminf(A2, B2), B3);
                    A0 = t0; A1 = t1; A2 = t2; A3 = t3;
                }
                uO = recv;
            }
            // lane 31's last write: step 285 (odd) -> A3 = R[127][127] (k = 254)
            if (l == 31) {
                g_dtw[b] = A3;
                __threadfence();
            }
            if (d == 0) bararrive(5, 288);     // free buf 0 for batch 3
        }
    }

    __syncthreads();

    if (tid == 0) {
        if (atomicAdd(&g_ctr, 1) == NCTA - 1) {
            __threadfence();
            // deterministic fixed-order reduction of g_dtw[0..511]
            float a0 = 0.f, a1 = 0.f, a2 = 0.f, a3 = 0.f;
            float a4 = 0.f, a5 = 0.f, a6 = 0.f, a7 = 0.f;
            for (int i = 0; i < BATCH; i += 32) {
                float4 v0 = *(const float4*)&g_dtw[i];
                float4 v1 = *(const float4*)&g_dtw[i + 4];
                float4 v2 = *(const float4*)&g_dtw[i + 8];
                float4 v3 = *(const float4*)&g_dtw[i + 12];
                float4 v4 = *(const float4*)&g_dtw[i + 16];
                float4 v5 = *(const float4*)&g_dtw[i + 20];
                float4 v6 = *(const float4*)&g_dtw[i + 24];
                float4 v7 = *(const float4*)&g_dtw[i + 28];
                a0 += (v0.x + v0.y) + (v0.z + v0.w);
                a1 += (v1.x + v1.y) + (v1.z + v1.w);
                a2 += (v2.x + v2.y) + (v2.z + v2.w);
                a3 += (v3.x + v3.y) + (v3.z + v3.w);
                a4 += (v4.x + v4.y) + (v4.z + v4.w);
                a5 += (v5.x + v5.y) + (v5.z + v5.w);
                a6 += (v6.x + v6.y) + (v6.z + v6.w);
                a7 += (v7.x + v7.y) + (v7.z + v7.w);
            }
            float s = ((a0 + a1) + (a2 + a3)) + ((a4 + a5) + (a6 + a7));
            float E = s * (1.0f / (float)BATCH);
            out[0] = E;
            out[1] = 10.0f * sqrtf(E + 1e-10f);
            g_ctr = 0;   // reset for graph replay
        }
    }
}

extern "C" void kernel_launch(void* const* d_in, const int* in_sizes, int n_in,
                              void* d_out, int out_size) {
    const float* X = (const float*)d_in[0];   // outputs
    const float* Y = (const float*)d_in[1];   // targets
    float* out = (float*)d_out;

    cudaFuncSetAttribute(fused_kernel, cudaFuncAttributeMaxDynamicSharedMemorySize,
                         SM_DYN_BYTES);

    fused_kernel<<<NCTA, 384, SM_DYN_BYTES>>>(X, Y, out);
}

// round 10
// speedup vs baseline: 1.4984x; 1.1482x over previous
#include <cuda_runtime.h>
#include <cuda_fp16.h>
#include <cuda_bf16.h>
#include <cstdint>
#include <math.h>

#define BATCH 512
#define NSEQ  128
#define DDIM  128
#define BIGF 1e30f

#define NCTA  148
#define NDIAG 255           // 2*NSEQ-1
#define PH    136           // bf16 staging pitch in halves (272 B/row)
#define DP_H  136           // diag pitch in halves (272 B; 8B-aligned, proven R9)
#define BUF_WORDS (NSEQ * PH)                  // per-matrix halves = 17408; buffer holds 2
#define SM_DYN_BYTES (3 * 2 * BUF_WORDS * 2)   // 3 buffers x 69632 B = 208896 B

// Named barriers: full[ib] = 1+ib (ib=0..3, count 288), empty(buf0 reuse) = 5
// (count 288), MMA-internal = 7 (count 256).

__device__ float g_dtw[BATCH];
__device__ int   g_ctr = 0;

__device__ __forceinline__ void barsync(int id, int cnt) {
    asm volatile("bar.sync %0, %1;" :: "r"(id), "r"(cnt) : "memory");
}
__device__ __forceinline__ void bararrive(int id, int cnt) {
    asm volatile("bar.arrive %0, %1;" :: "r"(id), "r"(cnt) : "memory");
}
__device__ __forceinline__ uint32_t f22bf(float lo, float hi) {
    uint32_t r;
    asm("cvt.rn.bf16x2.f32 %0, %1, %2;" : "=r"(r) : "f"(hi), "f"(lo));
    return r;
}
__device__ __forceinline__ float2 bf22f2(uint32_t u) {
    __nv_bfloat162 h = *(__nv_bfloat162*)&u;
    return __bfloat1622float2(h);
}
__device__ __forceinline__ void mma_bf16(float c[4], const uint32_t a[4],
                                         const uint32_t b[2]) {
    asm volatile(
        "mma.sync.aligned.m16n8k16.row.col.f32.bf16.bf16.f32 "
        "{%0,%1,%2,%3}, {%4,%5,%6,%7}, {%8,%9}, {%0,%1,%2,%3};\n"
        : "+f"(c[0]), "+f"(c[1]), "+f"(c[2]), "+f"(c[3])
        : "r"(a[0]), "r"(a[1]), "r"(a[2]), "r"(a[3]), "r"(b[0]), "r"(b[1]));
}

__global__ __launch_bounds__(384, 1) void fused_kernel(const float* __restrict__ X,
                                                       const float* __restrict__ Y,
                                                       float* __restrict__ out) {
    extern __shared__ __align__(16) __nv_bfloat16 smh[];
    __shared__ float xxs[NSEQ], yys[NSEQ];

    const int tid = threadIdx.x, w = tid >> 5, lane = tid & 31;
    const int c = blockIdx.x;
    const int nb = (c < BATCH - 3 * NCTA) ? 4 : 3;   // 4 for c<68, else 3

    if (w < 8) {
        // ================= MMA role: threads 0..255 =================
        const int qr = lane >> 2, qc = lane & 3;
        const int m0 = (w & 1) * 64, n0 = (w >> 1) * 32;

        for (int ib = 0; ib < nb; ib++) {
            const int b = ib * NCTA + c;
            const int p = ib % 3;
            __nv_bfloat16* buf = smh + p * 2 * BUF_WORDS;
            __nv_bfloat16* Xs = buf;                 // [128][136] bf16
            __nv_bfloat16* Ys = buf + BUF_WORDS;     // [128][136] bf16

            if (ib == 3) barsync(5, 288);            // wait DP warp 0 to free buf 0

            // ---- stage FULL X,Y as bf16 (single phase, coalesced LDG.128) ----
            const float* Xg = X + (size_t)b * NSEQ * DDIM;
            const float* Yg = Y + (size_t)b * NSEQ * DDIM;
            #pragma unroll
            for (int s = 0; s < 16; s++) {
                int idx = s * 256 + tid;            // 0..4095 float4s
                int r = idx >> 5, c4 = (idx & 31) << 2;
                float4 xv = *(const float4*)(Xg + r * DDIM + c4);
                float4 yv = *(const float4*)(Yg + r * DDIM + c4);
                uint2 xp = make_uint2(f22bf(xv.x, xv.y), f22bf(xv.z, xv.w));
                uint2 yp = make_uint2(f22bf(yv.x, yv.y), f22bf(yv.z, yv.w));
                *(uint2*)&Xs[r * PH + c4] = xp;
                *(uint2*)&Ys[r * PH + c4] = yp;
            }
            barsync(7, 256);

            // ---- norms from bf16 smem (1 row per thread) ----
            {
                int r = tid & 127;
                const __nv_bfloat16* src = (tid < NSEQ) ? Xs : Ys;
                float s = 0.f;
                #pragma unroll
                for (int cc = 0; cc < DDIM; cc += 8) {
                    uint4 v = *(const uint4*)&src[r * PH + cc];
                    float2 f0 = bf22f2(v.x), f1 = bf22f2(v.y);
                    float2 f2 = bf22f2(v.z), f3 = bf22f2(v.w);
                    s = fmaf(f0.x, f0.x, fmaf(f0.y, f0.y, s));
                    s = fmaf(f1.x, f1.x, fmaf(f1.y, f1.y, s));
                    s = fmaf(f2.x, f2.x, fmaf(f2.y, f2.y, s));
                    s = fmaf(f3.x, f3.x, fmaf(f3.y, f3.y, s));
                }
                if (tid < NSEQ) xxs[r] = s; else yys[r] = s;
            }

            // ---- bf16 HMMA mainloop: 8 K-steps of 16 ----
            float acc[4][4][4];
            #pragma unroll
            for (int mt = 0; mt < 4; mt++)
                #pragma unroll
                for (int nt = 0; nt < 4; nt++)
                    #pragma unroll
                    for (int r = 0; r < 4; r++) acc[mt][nt][r] = 0.f;

            #pragma unroll 2
            for (int k0 = 0; k0 < DDIM; k0 += 16) {
                uint32_t aF[4][4], bF[4][2];
                #pragma unroll
                for (int mt = 0; mt < 4; mt++) {
                    const __nv_bfloat16* ab = &Xs[(m0 + mt * 16 + qr) * PH + k0 + 2 * qc];
                    aF[mt][0] = *(const uint32_t*)(ab);
                    aF[mt][1] = *(const uint32_t*)(ab + 8 * PH);
                    aF[mt][2] = *(const uint32_t*)(ab + 8);
                    aF[mt][3] = *(const uint32_t*)(ab + 8 * PH + 8);
                }
                #pragma unroll
                for (int nt = 0; nt < 4; nt++) {
                    const __nv_bfloat16* bb = &Ys[(n0 + nt * 8 + qr) * PH + k0 + 2 * qc];
                    bF[nt][0] = *(const uint32_t*)(bb);
                    bF[nt][1] = *(const uint32_t*)(bb + 8);
                }
                #pragma unroll
                for (int mt = 0; mt < 4; mt++)
                    #pragma unroll
                    for (int nt = 0; nt < 4; nt++)
                        mma_bf16(acc[mt][nt], aF[mt], bF[nt]);
            }
            barsync(7, 256);   // staging reads done; buf reusable; norms visible

            // ---- fill diag area with fp16 +inf (invalid cells self-mask) ----
            {
                uint4 inf4 = make_uint4(0x7C007C00u, 0x7C007C00u, 0x7C007C00u, 0x7C007C00u);
                uint4* bv = (uint4*)buf;
                #pragma unroll
                for (int i = tid; i < NDIAG * DP_H * 2 / 16; i += 256) bv[i] = inf4;
            }
            barsync(7, 256);

            // ---- epilogue: D = xx + yy - 2*xy -> fp16, diag-major ----
            __half* Dd = (__half*)buf;   // [255][136] halves = 69360 B
            #pragma unroll
            for (int mt = 0; mt < 4; mt++) {
                int i0 = m0 + mt * 16 + qr;
                float xv0 = xxs[i0], xv1 = xxs[i0 + 8];
                #pragma unroll
                for (int nt = 0; nt < 4; nt++) {
                    int j0 = n0 + nt * 8 + 2 * qc;
                    float yv0 = yys[j0], yv1 = yys[j0 + 1];
                    const float* cA = acc[mt][nt];
                    Dd[(i0 + j0)         * DP_H + j0]     = __float2half(xv0 + yv0 - 2.f * cA[0]);
                    Dd[(i0 + j0 + 1)     * DP_H + j0 + 1] = __float2half(xv0 + yv1 - 2.f * cA[1]);
                    Dd[(i0 + 8 + j0)     * DP_H + j0]     = __float2half(xv1 + yv0 - 2.f * cA[2]);
                    Dd[(i0 + 8 + j0 + 1) * DP_H + j0 + 1] = __float2half(xv1 + yv1 - 2.f * cA[3]);
                }
            }
            barsync(7, 256);               // epilogue complete
            bararrive(1 + ib, 288);        // signal full[ib]
        }
    } else {
        // ========== DP role: warps 8..11, one batch each, skewed wavefront ==========
        const int d = w - 8, l = lane;
        if (d < nb) {
            const int b = d * NCTA + c;
            const __half* Dd = (const __half*)(smh + (d % 3) * 2 * BUF_WORDS);

            barsync(1 + d, 288);           // wait full[d]

            // Skew: lane l processes diagonal k = s - l at step s. Lane owns
            // columns j = 4l..4l+3. Invalid cells are +inf (self-masking);
            // boundary shfl has 2 steps of slack off the critical path.
            float A0 = BIGF, A1 = BIGF, A2 = BIGF, A3 = BIGF;
            float B0 = BIGF, B1 = BIGF, B2 = BIGF, B3 = BIGF;
            float uE = BIGF, uO = BIGF;
            const int zstep = (l == 0) ? 0 : -1;

            const __half* base = Dd + 4 * l;
            auto ldD = [&](int s_) -> uint2 {
                int k = s_ - l;
                k = k < 0 ? 0 : (k > NDIAG - 1 ? NDIAG - 1 : k);
                return *(const uint2*)(base + k * DP_H);
            };
            uint2 q0 = ldD(0), q1 = ldD(1);

            #pragma unroll 1
            for (int s = 0; s < 286; s += 2) {
                float recv = __shfl_up_sync(0xffffffffu, A3, 1);
                recv = (l == 0) ? BIGF : recv;
                uint2 dq = q0; q0 = ldD(s + 2);
                float2 f01 = __half22float2(*(__half2*)&dq.x);
                float2 f23 = __half22float2(*(__half2*)&dq.y);
                {
                    float dg0 = (s == zstep) ? 0.f : uE;
                    float t0 = f01.x + fminf(fminf(dg0, uO), A0);
                    float t1 = f01.y + fminf(fminf(B0, A0), A1);
                    float t2 = f23.x + fminf(fminf(B1, A1), A2);
                    float t3 = f23.y + fminf(fminf(B2, A2), A3);
                    B0 = t0; B1 = t1; B2 = t2; B3 = t3;
                }
                uE = recv;

                recv = __shfl_up_sync(0xffffffffu, B3, 1);
                recv = (l == 0) ? BIGF : recv;
                dq = q1; q1 = ldD(s + 3);
                f01 = __half22float2(*(__half2*)&dq.x);
                f23 = __half22float2(*(__half2*)&dq.y);
                {
                    float t0 = f01.x + fminf(fminf(uO, uE), B0);
                    float t1 = f01.y + fminf(fminf(A0, B0), B1);
                    float t2 = f23.x + fminf(fminf(A1, B1), B2);
                    float t3 = f23.y + fminf(fminf(A2, B2), B3);
                    A0 = t0; A1 = t1; A2 = t2; A3 = t3;
                }
                uO = recv;
            }
            if (l == 31) {
                g_dtw[b] = A3;             // R[127][127] (k = 254)
                __threadfence();
            }
            if (d == 0) bararrive(5, 288); // free buf 0 for batch 3
        }
    }

    __syncthreads();

    if (tid == 0) {
        if (atomicAdd(&g_ctr, 1) == NCTA - 1) {
            __threadfence();
            // deterministic fixed-order reduction of g_dtw[0..511]
            float a0 = 0.f, a1 = 0.f, a2 = 0.f, a3 = 0.f;
            float a4 = 0.f, a5 = 0.f, a6 = 0.f, a7 = 0.f;
            for (int i = 0; i < BATCH; i += 32) {
                float4 v0 = *(const float4*)&g_dtw[i];
                float4 v1 = *(const float4*)&g_dtw[i + 4];
                float4 v2 = *(const float4*)&g_dtw[i + 8];
                float4 v3 = *(const float4*)&g_dtw[i + 12];
                float4 v4 = *(const float4*)&g_dtw[i + 16];
                float4 v5 = *(const float4*)&g_dtw[i + 20];
                float4 v6 = *(const float4*)&g_dtw[i + 24];
                float4 v7 = *(const float4*)&g_dtw[i + 28];
                a0 += (v0.x + v0.y) + (v0.z + v0.w);
                a1 += (v1.x + v1.y) + (v1.z + v1.w);
                a2 += (v2.x + v2.y) + (v2.z + v2.w);
                a3 += (v3.x + v3.y) + (v3.z + v3.w);
                a4 += (v4.x + v4.y) + (v4.z + v4.w);
                a5 += (v5.x + v5.y) + (v5.z + v5.w);
                a6 += (v6.x + v6.y) + (v6.z + v6.w);
                a7 += (v7.x + v7.y) + (v7.z + v7.w);
            }
            float s = ((a0 + a1) + (a2 + a3)) + ((a4 + a5) + (a6 + a7));
            float E = s * (1.0f / (float)BATCH);
            out[0] = E;
            out[1] = 10.0f * sqrtf(E + 1e-10f);
            g_ctr = 0;   // reset for graph replay
        }
    }
}

extern "C" void kernel_launch(void* const* d_in, const int* in_sizes, int n_in,
                              void* d_out, int out_size) {
    const float* X = (const float*)d_in[0];   // outputs
    const float* Y = (const float*)d_in[1];   // targets
    float* out = (float*)d_out;

    cudaFuncSetAttribute(fused_kernel, cudaFuncAttributeMaxDynamicSharedMemorySize,
                         SM_DYN_BYTES);

    fused_kernel<<<NCTA, 384, SM_DYN_BYTES>>>(X, Y, out);
}

// round 11
// speedup vs baseline: 1.4996x; 1.0008x over previous
#include <cuda_runtime.h>
#include <cuda_fp16.h>
#include <cuda_bf16.h>
#include <cstdint>
#include <math.h>

#define BATCH 512
#define NSEQ  128
#define DDIM  128
#define BIGF 1e30f

#define NCTA  296           // 2 CTAs per SM (148 SMs)
#define NDIAG 255           // 2*NSEQ-1
#define PH    136           // bf16 staging pitch in halves (272 B/row)
#define DP_H  136           // diag pitch in halves (proven: DP load 2-way, epi conflict-free)
#define BUF_WORDS (NSEQ * PH)                // per-matrix halves = 17408
#define SM_DYN_BYTES (2 * BUF_WORDS * 2)     // one 69632 B buffer per CTA

__device__ float g_dtw[BATCH];
__device__ int   g_ctr = 0;

__device__ __forceinline__ uint32_t f22bf(float lo, float hi) {
    uint32_t r;
    asm("cvt.rn.bf16x2.f32 %0, %1, %2;" : "=r"(r) : "f"(hi), "f"(lo));
    return r;
}
__device__ __forceinline__ float2 bf22f2(uint32_t u) {
    __nv_bfloat162 h = *(__nv_bfloat162*)&u;
    return __bfloat1622float2(h);
}
__device__ __forceinline__ void mma_bf16(float c[4], const uint32_t a[4],
                                         const uint32_t b[2]) {
    asm volatile(
        "mma.sync.aligned.m16n8k16.row.col.f32.bf16.bf16.f32 "
        "{%0,%1,%2,%3}, {%4,%5,%6,%7}, {%8,%9}, {%0,%1,%2,%3};\n"
        : "+f"(c[0]), "+f"(c[1]), "+f"(c[2]), "+f"(c[3])
        : "r"(a[0]), "r"(a[1]), "r"(a[2]), "r"(a[3]), "r"(b[0]), "r"(b[1]));
}

__global__ __launch_bounds__(256, 2) void fused_kernel(const float* __restrict__ X,
                                                       const float* __restrict__ Y,
                                                       float* __restrict__ out) {
    extern __shared__ __align__(16) __nv_bfloat16 smh[];
    __shared__ float xxs[NSEQ], yys[NSEQ];

    const int tid = threadIdx.x, w = tid >> 5, lane = tid & 31;
    const int c = blockIdx.x;
    const int nb = (c < BATCH - NCTA) ? 2 : 1;      // c<216 -> 2 batches

    const int qr = lane >> 2, qc = lane & 3;
    const int m0 = (w & 1) * 64, n0 = (w >> 1) * 32;

    __nv_bfloat16* Xs = smh;                 // [128][136] bf16
    __nv_bfloat16* Ys = smh + BUF_WORDS;     // [128][136] bf16
    __half* Dd = (__half*)smh;               // [255][136] fp16 (reuses buffer)

    for (int ib = 0; ib < nb; ib++) {
        const int b = c + ib * NCTA;

        // ---- stage FULL X,Y as bf16 (single phase, coalesced LDG.128) ----
        const float* Xg = X + (size_t)b * NSEQ * DDIM;
        const float* Yg = Y + (size_t)b * NSEQ * DDIM;
        #pragma unroll 4
        for (int s = 0; s < 16; s++) {
            int idx = s * 256 + tid;            // 0..4095 float4s
            int r = idx >> 5, c4 = (idx & 31) << 2;
            float4 xv = *(const float4*)(Xg + r * DDIM + c4);
            float4 yv = *(const float4*)(Yg + r * DDIM + c4);
            uint2 xp = make_uint2(f22bf(xv.x, xv.y), f22bf(xv.z, xv.w));
            uint2 yp = make_uint2(f22bf(yv.x, yv.y), f22bf(yv.z, yv.w));
            *(uint2*)&Xs[r * PH + c4] = xp;
            *(uint2*)&Ys[r * PH + c4] = yp;
        }
        __syncthreads();

        // ---- norms from bf16 smem (1 row per thread; threads 0-127 X, 128-255 Y) ----
        {
            int r = tid & 127;
            const __nv_bfloat16* src = (tid < NSEQ) ? Xs : Ys;
            float s = 0.f;
            #pragma unroll
            for (int cc = 0; cc < DDIM; cc += 8) {
                uint4 v = *(const uint4*)&src[r * PH + cc];
                float2 f0 = bf22f2(v.x), f1 = bf22f2(v.y);
                float2 f2 = bf22f2(v.z), f3 = bf22f2(v.w);
                s = fmaf(f0.x, f0.x, fmaf(f0.y, f0.y, s));
                s = fmaf(f1.x, f1.x, fmaf(f1.y, f1.y, s));
                s = fmaf(f2.x, f2.x, fmaf(f2.y, f2.y, s));
                s = fmaf(f3.x, f3.x, fmaf(f3.y, f3.y, s));
            }
            if (tid < NSEQ) xxs[r] = s; else yys[r] = s;
        }

        // ---- bf16 HMMA mainloop: 8 K-steps of 16, warp tile 64x32 ----
        float acc[4][4][4];
        #pragma unroll
        for (int mt = 0; mt < 4; mt++)
            #pragma unroll
            for (int nt = 0; nt < 4; nt++)
                #pragma unroll
                for (int r = 0; r < 4; r++) acc[mt][nt][r] = 0.f;

        #pragma unroll 2
        for (int k0 = 0; k0 < DDIM; k0 += 16) {
            uint32_t aF[4][4], bF[4][2];
            #pragma unroll
            for (int mt = 0; mt < 4; mt++) {
                const __nv_bfloat16* ab = &Xs[(m0 + mt * 16 + qr) * PH + k0 + 2 * qc];
                aF[mt][0] = *(const uint32_t*)(ab);
                aF[mt][1] = *(const uint32_t*)(ab + 8 * PH);
                aF[mt][2] = *(const uint32_t*)(ab + 8);
                aF[mt][3] = *(const uint32_t*)(ab + 8 * PH + 8);
            }
            #pragma unroll
            for (int nt = 0; nt < 4; nt++) {
                const __nv_bfloat16* bb = &Ys[(n0 + nt * 8 + qr) * PH + k0 + 2 * qc];
                bF[nt][0] = *(const uint32_t*)(bb);
                bF[nt][1] = *(const uint32_t*)(bb + 8);
            }
            #pragma unroll
            for (int mt = 0; mt < 4; mt++)
                #pragma unroll
                for (int nt = 0; nt < 4; nt++)
                    mma_bf16(acc[mt][nt], aF[mt], bF[nt]);
        }
        __syncthreads();   // staging reads done; buffer reusable; norms visible

        // ---- fill diag area with fp16 +inf (invalid cells self-mask in DP) ----
        {
            uint4 inf4 = make_uint4(0x7C007C00u, 0x7C007C00u, 0x7C007C00u, 0x7C007C00u);
            uint4* bv = (uint4*)smh;
            #pragma unroll
            for (int i = tid; i < NDIAG * DP_H * 2 / 16; i += 256) bv[i] = inf4;
        }
        __syncthreads();

        // ---- epilogue: D = xx + yy - 2*xy -> fp16, diag-major ----
        #pragma unroll
        for (int mt = 0; mt < 4; mt++) {
            int i0 = m0 + mt * 16 + qr;
            float xv0 = xxs[i0], xv1 = xxs[i0 + 8];
            #pragma unroll
            for (int nt = 0; nt < 4; nt++) {
                int j0 = n0 + nt * 8 + 2 * qc;
                float yv0 = yys[j0], yv1 = yys[j0 + 1];
                const float* cA = acc[mt][nt];
                Dd[(i0 + j0)         * DP_H + j0]     = __float2half(xv0 + yv0 - 2.f * cA[0]);
                Dd[(i0 + j0 + 1)     * DP_H + j0 + 1] = __float2half(xv0 + yv1 - 2.f * cA[1]);
                Dd[(i0 + 8 + j0)     * DP_H + j0]     = __float2half(xv1 + yv0 - 2.f * cA[2]);
                Dd[(i0 + 8 + j0 + 1) * DP_H + j0 + 1] = __float2half(xv1 + yv1 - 2.f * cA[3]);
            }
        }
        __syncthreads();

        // ---- soft-DTW DP: warp 0 only (skewed wavefront, proven R9/R10) ----
        if (w == 0) {
            const int l = lane;
            float A0 = BIGF, A1 = BIGF, A2 = BIGF, A3 = BIGF;
            float B0 = BIGF, B1 = BIGF, B2 = BIGF, B3 = BIGF;
            float uE = BIGF, uO = BIGF;
            const int zstep = (l == 0) ? 0 : -1;

            const __half* base = (const __half*)Dd + 4 * l;
            auto ldD = [&](int s_) -> uint2 {
                int k = s_ - l;
                k = k < 0 ? 0 : (k > NDIAG - 1 ? NDIAG - 1 : k);
                return *(const uint2*)(base + k * DP_H);
            };
            uint2 q0 = ldD(0), q1 = ldD(1);

            #pragma unroll 1
            for (int s = 0; s < 286; s += 2) {
                float recv = __shfl_up_sync(0xffffffffu, A3, 1);
                recv = (l == 0) ? BIGF : recv;
                uint2 dq = q0; q0 = ldD(s + 2);
                float2 f01 = __half22float2(*(__half2*)&dq.x);
                float2 f23 = __half22float2(*(__half2*)&dq.y);
                {
                    float dg0 = (s == zstep) ? 0.f : uE;
                    float t0 = f01.x + fminf(fminf(dg0, uO), A0);
                    float t1 = f01.y + fminf(fminf(B0, A0), A1);
                    float t2 = f23.x + fminf(fminf(B1, A1), A2);
                    float t3 = f23.y + fminf(fminf(B2, A2), A3);
                    B0 = t0; B1 = t1; B2 = t2; B3 = t3;
                }
                uE = recv;

                recv = __shfl_up_sync(0xffffffffu, B3, 1);
                recv = (l == 0) ? BIGF : recv;
                dq = q1; q1 = ldD(s + 3);
                f01 = __half22float2(*(__half2*)&dq.x);
                f23 = __half22float2(*(__half2*)&dq.y);
                {
                    float t0 = f01.x + fminf(fminf(uO, uE), B0);
                    float t1 = f01.y + fminf(fminf(A0, B0), B1);
                    float t2 = f23.x + fminf(fminf(A1, B1), B2);
                    float t3 = f23.y + fminf(fminf(A2, B2), B3);
                    A0 = t0; A1 = t1; A2 = t2; A3 = t3;
                }
                uO = recv;
            }
            if (l == 31) g_dtw[b] = A3;   // R[127][127] (k = 254)
        }
        __syncthreads();   // DP done; buffer free for next batch
    }

    if (tid == 0) {
        __threadfence();
        if (atomicAdd(&g_ctr, 1) == NCTA - 1) {
            __threadfence();
            // deterministic fixed-order reduction of g_dtw[0..511]
            float a0 = 0.f, a1 = 0.f, a2 = 0.f, a3 = 0.f;
            float a4 = 0.f, a5 = 0.f, a6 = 0.f, a7 = 0.f;
            for (int i = 0; i < BATCH; i += 32) {
                float4 v0 = *(const float4*)&g_dtw[i];
                float4 v1 = *(const float4*)&g_dtw[i + 4];
                float4 v2 = *(const float4*)&g_dtw[i + 8];
                float4 v3 = *(const float4*)&g_dtw[i + 12];
                float4 v4 = *(const float4*)&g_dtw[i + 16];
                float4 v5 = *(const float4*)&g_dtw[i + 20];
                float4 v6 = *(const float4*)&g_dtw[i + 24];
                float4 v7 = *(const float4*)&g_dtw[i + 28];
                a0 += (v0.x + v0.y) + (v0.z + v0.w);
                a1 += (v1.x + v1.y) + (v1.z + v1.w);
                a2 += (v2.x + v2.y) + (v2.z + v2.w);
                a3 += (v3.x + v3.y) + (v3.z + v3.w);
                a4 += (v4.x + v4.y) + (v4.z + v4.w);
                a5 += (v5.x + v5.y) + (v5.z + v5.w);
                a6 += (v6.x + v6.y) + (v6.z + v6.w);
                a7 += (v7.x + v7.y) + (v7.z + v7.w);
            }
            float s = ((a0 + a1) + (a2 + a3)) + ((a4 + a5) + (a6 + a7));
            float E = s * (1.0f / (float)BATCH);
            out[0] = E;
            out[1] = 10.0f * sqrtf(E + 1e-10f);
            g_ctr = 0;   // reset for graph replay
        }
    }
}

extern "C" void kernel_launch(void* const* d_in, const int* in_sizes, int n_in,
                              void* d_out, int out_size) {
    const float* X = (const float*)d_in[0];   // outputs
    const float* Y = (const float*)d_in[1];   // targets
    float* out = (float*)d_out;

    cudaFuncSetAttribute(fused_kernel, cudaFuncAttributeMaxDynamicSharedMemorySize,
                         SM_DYN_BYTES);

    fused_kernel<<<NCTA, 256, SM_DYN_BYTES>>>(X, Y, out);
}

// round 12
// speedup vs baseline: 1.5720x; 1.0483x over previous
#include <cuda_runtime.h>
#include <cuda_fp16.h>
#include <cuda_bf16.h>
#include <cstdint>
#include <math.h>

#define BATCH 512
#define NSEQ  128
#define DDIM  128
#define BIGF 1e30f

#define NCTA  296           // 2 CTAs per SM (148 SMs)
#define NDIAG 255           // 2*NSEQ-1
#define PH    136           // bf16 staging pitch in halves (272 B/row; ldmatrix conflict-free)
#define DP_H  136           // diag pitch in halves (proven: DP load 2-way, epi conflict-free)
#define BUF_WORDS (NSEQ * PH)                // per-matrix halves = 17408
#define SM_DYN_BYTES (2 * BUF_WORDS * 2)     // one 69632 B buffer per CTA

__device__ float g_dtw[BATCH];
__device__ int   g_ctr = 0;

__device__ __forceinline__ uint32_t smem_u32(const void* p) {
    uint32_t a;
    asm("{ .reg .u64 t; cvta.to.shared.u64 t, %1; cvt.u32.u64 %0, t; }" : "=r"(a) : "l"(p));
    return a;
}
__device__ __forceinline__ uint32_t f22bf(float lo, float hi) {
    uint32_t r;
    asm("cvt.rn.bf16x2.f32 %0, %1, %2;" : "=r"(r) : "f"(hi), "f"(lo));
    return r;
}
__device__ __forceinline__ float2 bf22f2(uint32_t u) {
    __nv_bfloat162 h = *(__nv_bfloat162*)&u;
    return __bfloat1622float2(h);
}
__device__ __forceinline__ void ldmx4(uint32_t* r, uint32_t addr) {
    asm volatile("ldmatrix.sync.aligned.m8n8.x4.shared.b16 {%0,%1,%2,%3}, [%4];"
                 : "=r"(r[0]), "=r"(r[1]), "=r"(r[2]), "=r"(r[3]) : "r"(addr));
}
__device__ __forceinline__ void mma_bf16(float c[4], const uint32_t a[4],
                                         const uint32_t b[2]) {
    asm volatile(
        "mma.sync.aligned.m16n8k16.row.col.f32.bf16.bf16.f32 "
        "{%0,%1,%2,%3}, {%4,%5,%6,%7}, {%8,%9}, {%0,%1,%2,%3};\n"
        : "+f"(c[0]), "+f"(c[1]), "+f"(c[2]), "+f"(c[3])
        : "r"(a[0]), "r"(a[1]), "r"(a[2]), "r"(a[3]), "r"(b[0]), "r"(b[1]));
}

__global__ __launch_bounds__(256, 2) void fused_kernel(const float* __restrict__ X,
                                                       const float* __restrict__ Y,
                                                       float* __restrict__ out) {
    extern __shared__ __align__(16) __nv_bfloat16 smh[];
    __shared__ float xxs[NSEQ], yys[NSEQ];

    const int tid = threadIdx.x, w = tid >> 5, lane = tid & 31;
    const int c = blockIdx.x;
    const int nb = (c < BATCH - NCTA) ? 2 : 1;      // c<216 -> 2 batches

    const int qr = lane >> 2, qc = lane & 3;
    const int m0 = (w & 1) * 64, n0 = (w >> 1) * 32;

    __nv_bfloat16* Xs = smh;                 // [128][136] bf16
    __nv_bfloat16* Ys = smh + BUF_WORDS;     // [128][136] bf16
    __half* Dd = (__half*)smh;               // [255][136] fp16 (reuses buffer)

    // ldmatrix source addresses (constant across k; add 2*k0 bytes per step)
    // A tile mt: lanes l -> row m0+mt*16+(l&15), col-half (l>>4)
    // B pair j (n-tiles 2j,2j+1): lanes l -> row n0+(2j+(l>>4))*8+(l&7), col-half (l>>3)&1
    const uint32_t xs_a = smem_u32(Xs);
    uint32_t aAddr[4], bAddr[2];
    #pragma unroll
    for (int mt = 0; mt < 4; mt++)
        aAddr[mt] = xs_a + (uint32_t)(((m0 + mt * 16 + (lane & 15)) * PH + (lane >> 4) * 8) * 2);
    const uint32_t ys_a = smem_u32(Ys);
    #pragma unroll
    for (int j = 0; j < 2; j++)
        bAddr[j] = ys_a + (uint32_t)(((n0 + (2 * j + (lane >> 4)) * 8 + (lane & 7)) * PH
                                      + ((lane >> 3) & 1) * 8) * 2);

    for (int ib = 0; ib < nb; ib++) {
        const int b = c + ib * NCTA;

        // ---- stage FULL X,Y as bf16 (deep-MLP coalesced LDG.128) ----
        const float* Xg = X + (size_t)b * NSEQ * DDIM;
        const float* Yg = Y + (size_t)b * NSEQ * DDIM;
        #pragma unroll 8
        for (int s = 0; s < 16; s++) {
            int idx = s * 256 + tid;            // 0..4095 float4s
            int r = idx >> 5, c4 = (idx & 31) << 2;
            float4 xv = *(const float4*)(Xg + r * DDIM + c4);
            float4 yv = *(const float4*)(Yg + r * DDIM + c4);
            uint2 xp = make_uint2(f22bf(xv.x, xv.y), f22bf(xv.z, xv.w));
            uint2 yp = make_uint2(f22bf(yv.x, yv.y), f22bf(yv.z, yv.w));
            *(uint2*)&Xs[r * PH + c4] = xp;
            *(uint2*)&Ys[r * PH + c4] = yp;
        }
        __syncthreads();

        // ---- norms from bf16 smem (1 row per thread) ----
        {
            int r = tid & 127;
            const __nv_bfloat16* src = (tid < NSEQ) ? Xs : Ys;
            float s = 0.f;
            #pragma unroll
            for (int cc = 0; cc < DDIM; cc += 8) {
                uint4 v = *(const uint4*)&src[r * PH + cc];
                float2 f0 = bf22f2(v.x), f1 = bf22f2(v.y);
                float2 f2 = bf22f2(v.z), f3 = bf22f2(v.w);
                s = fmaf(f0.x, f0.x, fmaf(f0.y, f0.y, s));
                s = fmaf(f1.x, f1.x, fmaf(f1.y, f1.y, s));
                s = fmaf(f2.x, f2.x, fmaf(f2.y, f2.y, s));
                s = fmaf(f3.x, f3.x, fmaf(f3.y, f3.y, s));
            }
            if (tid < NSEQ) xxs[r] = s; else yys[r] = s;
        }

        // ---- bf16 HMMA mainloop: 8 K-steps of 16, fragments via ldmatrix.x4 ----
        float acc[4][4][4];
        #pragma unroll
        for (int mt = 0; mt < 4; mt++)
            #pragma unroll
            for (int nt = 0; nt < 4; nt++)
                #pragma unroll
                for (int r = 0; r < 4; r++) acc[mt][nt][r] = 0.f;

        #pragma unroll 2
        for (int k0 = 0; k0 < DDIM; k0 += 16) {
            uint32_t aF[4][4], bP[2][4];
            #pragma unroll
            for (int mt = 0; mt < 4; mt++) ldmx4(aF[mt], aAddr[mt] + 2 * k0);
            #pragma unroll
            for (int j = 0; j < 2; j++)    ldmx4(bP[j], bAddr[j] + 2 * k0);
            // bP[j] = {b(2j)[0], b(2j)[1], b(2j+1)[0], b(2j+1)[1]}
            #pragma unroll
            for (int mt = 0; mt < 4; mt++) {
                mma_bf16(acc[mt][0], aF[mt], &bP[0][0]);
                mma_bf16(acc[mt][1], aF[mt], &bP[0][2]);
                mma_bf16(acc[mt][2], aF[mt], &bP[1][0]);
                mma_bf16(acc[mt][3], aF[mt], &bP[1][2]);
            }
        }
        __syncthreads();   // staging reads done; buffer reusable; norms visible

        // ---- fill diag area with fp16 +inf (invalid cells self-mask in DP) ----
        {
            uint4 inf4 = make_uint4(0x7C007C00u, 0x7C007C00u, 0x7C007C00u, 0x7C007C00u);
            uint4* bv = (uint4*)smh;
            #pragma unroll
            for (int i = tid; i < NDIAG * DP_H * 2 / 16; i += 256) bv[i] = inf4;
        }
        __syncthreads();

        // ---- epilogue: D = xx + yy - 2*xy -> fp16, diag-major ----
        #pragma unroll
        for (int mt = 0; mt < 4; mt++) {
            int i0 = m0 + mt * 16 + qr;
            float xv0 = xxs[i0], xv1 = xxs[i0 + 8];
            #pragma unroll
            for (int nt = 0; nt < 4; nt++) {
                int j0 = n0 + nt * 8 + 2 * qc;
                float yv0 = yys[j0], yv1 = yys[j0 + 1];
                const float* cA = acc[mt][nt];
                Dd[(i0 + j0)         * DP_H + j0]     = __float2half(xv0 + yv0 - 2.f * cA[0]);
                Dd[(i0 + j0 + 1)     * DP_H + j0 + 1] = __float2half(xv0 + yv1 - 2.f * cA[1]);
                Dd[(i0 + 8 + j0)     * DP_H + j0]     = __float2half(xv1 + yv0 - 2.f * cA[2]);
                Dd[(i0 + 8 + j0 + 1) * DP_H + j0 + 1] = __float2half(xv1 + yv1 - 2.f * cA[3]);
            }
        }
        __syncthreads();

        // ---- soft-DTW DP: warp 0 only (skewed wavefront, proven R9-R11) ----
        if (w == 0) {
            const int l = lane;
            float A0 = BIGF, A1 = BIGF, A2 = BIGF, A3 = BIGF;
            float B0 = BIGF, B1 = BIGF, B2 = BIGF, B3 = BIGF;
            float uE = BIGF, uO = BIGF;
            const int zstep = (l == 0) ? 0 : -1;

            const __half* base = (const __half*)Dd + 4 * l;
            auto ldD = [&](int s_) -> uint2 {
                int k = s_ - l;
                k = k < 0 ? 0 : (k > NDIAG - 1 ? NDIAG - 1 : k);
                return *(const uint2*)(base + k * DP_H);
            };
            uint2 q0 = ldD(0), q1 = ldD(1);

            #pragma unroll 1
            for (int s = 0; s < 286; s += 2) {
                float recv = __shfl_up_sync(0xffffffffu, A3, 1);
                recv = (l == 0) ? BIGF : recv;
                uint2 dq = q0; q0 = ldD(s + 2);
                float2 f01 = __half22float2(*(__half2*)&dq.x);
                float2 f23 = __half22float2(*(__half2*)&dq.y);
                {
                    float dg0 = (s == zstep) ? 0.f : uE;
                    float t0 = f01.x + fminf(fminf(dg0, uO), A0);
                    float t1 = f01.y + fminf(fminf(B0, A0), A1);
                    float t2 = f23.x + fminf(fminf(B1, A1), A2);
                    float t3 = f23.y + fminf(fminf(B2, A2), A3);
                    B0 = t0; B1 = t1; B2 = t2; B3 = t3;
                }
                uE = recv;

                recv = __shfl_up_sync(0xffffffffu, B3, 1);
                recv = (l == 0) ? BIGF : recv;
                dq = q1; q1 = ldD(s + 3);
                f01 = __half22float2(*(__half2*)&dq.x);
                f23 = __half22float2(*(__half2*)&dq.y);
                {
                    float t0 = f01.x + fminf(fminf(uO, uE), B0);
                    float t1 = f01.y + fminf(fminf(A0, B0), B1);
                    float t2 = f23.x + fminf(fminf(A1, B1), B2);
                    float t3 = f23.y + fminf(fminf(A2, B2), B3);
                    A0 = t0; A1 = t1; A2 = t2; A3 = t3;
                }
                uO = recv;
            }
            if (l == 31) g_dtw[b] = A3;   // R[127][127] (k = 254)
        }
        __syncthreads();   // DP done; buffer free for next batch
    }

    if (tid == 0) {
        __threadfence();
        if (atomicAdd(&g_ctr, 1) == NCTA - 1) {
            __threadfence();
            // deterministic fixed-order reduction of g_dtw[0..511]
            float a0 = 0.f, a1 = 0.f, a2 = 0.f, a3 = 0.f;
            float a4 = 0.f, a5 = 0.f, a6 = 0.f, a7 = 0.f;
            for (int i = 0; i < BATCH; i += 32) {
                float4 v0 = *(const float4*)&g_dtw[i];
                float4 v1 = *(const float4*)&g_dtw[i + 4];
                float4 v2 = *(const float4*)&g_dtw[i + 8];
                float4 v3 = *(const float4*)&g_dtw[i + 12];
                float4 v4 = *(const float4*)&g_dtw[i + 16];
                float4 v5 = *(const float4*)&g_dtw[i + 20];
                float4 v6 = *(const float4*)&g_dtw[i + 24];
                float4 v7 = *(const float4*)&g_dtw[i + 28];
                a0 += (v0.x + v0.y) + (v0.z + v0.w);
                a1 += (v1.x + v1.y) + (v1.z + v1.w);
                a2 += (v2.x + v2.y) + (v2.z + v2.w);
                a3 += (v3.x + v3.y) + (v3.z + v3.w);
                a4 += (v4.x + v4.y) + (v4.z + v4.w);
                a5 += (v5.x + v5.y) + (v5.z + v5.w);
                a6 += (v6.x + v6.y) + (v6.z + v6.w);
                a7 += (v7.x + v7.y) + (v7.z + v7.w);
            }
            float s = ((a0 + a1) + (a2 + a3)) + ((a4 + a5) + (a6 + a7));
            float E = s * (1.0f / (float)BATCH);
            out[0] = E;
            out[1] = 10.0f * sqrtf(E + 1e-10f);
            g_ctr = 0;   // reset for graph replay
        }
    }
}

extern "C" void kernel_launch(void* const* d_in, const int* in_sizes, int n_in,
                              void* d_out, int out_size) {
    const float* X = (const float*)d_in[0];   // outputs
    const float* Y = (const float*)d_in[1];   // targets
    float* out = (float*)d_out;

    cudaFuncSetAttribute(fused_kernel, cudaFuncAttributeMaxDynamicSharedMemorySize,
                         SM_DYN_BYTES);

    fused_kernel<<<NCTA, 256, SM_DYN_BYTES>>>(X, Y, out);
}